// round 17
// baseline (speedup 1.0000x reference)
#include <cuda_runtime.h>
#include <math_constants.h>

// Single-query attention: y = softmax(K @ q) @ V   (fp32, M=131072, D=256)
// Pass1: persistent single-wave (592 = 148 SM x 4 CTAs), RB=4 two-phase
// body, ~6.6 TB/s (confirmed achieved-BW ceiling across all structures).
// Publishes global max via order-preserving atomicMax (1/CTA).
// Tail: 128 blocks x 2 columns each -- ml loads + exp factors amortized
// over 2 columns, joint (ll,acc0,acc1) reduction, last-arriver reset.

#define M_TOTAL   131072
#define DIM       256
#define NCTA      592                      // 148 * 4, one wave
#define NWARPS    8
#define RB        4                        // rows per warp per chunk
#define CHUNK_ROWS (NWARPS * RB)           // 32
#define NCHUNKS   (M_TOTAL / CHUNK_ROWS)   // 4096

#define TAIL_BLOCKS (DIM / 2)              // 128 blocks, 2 columns each

// Scratch (allocation-free): ~620 KB
__device__ float  g_partT[DIM][NCTA];      // transposed: [column][cta]
__device__ float2 g_ml[NCTA];              // packed (m, l)
__device__ unsigned int g_gmax_u;          // order-preserving encoded max (0 = -inf)
__device__ unsigned int g_cnt;             // tail completion counter

// Order-preserving float <-> uint (monotone for all finite floats)
__device__ __forceinline__ unsigned int enc_f(float f) {
    unsigned int b = __float_as_uint(f);
    return (b & 0x80000000u) ? ~b : (b | 0x80000000u);
}
__device__ __forceinline__ float dec_f(unsigned int u) {
    unsigned int b = (u & 0x80000000u) ? (u ^ 0x80000000u) : ~u;
    return __uint_as_float(b);
}

__global__ __launch_bounds__(256, 4)
void sqa_pass1(const float* __restrict__ q,
               const float* __restrict__ K,
               const float* __restrict__ V) {
    const int tid  = threadIdx.x;
    const int warp = tid >> 5;
    const int lane = tid & 31;
    const int bid  = blockIdx.x;

    const float4 q0 = reinterpret_cast<const float4*>(q)[lane];
    const float4 q1 = reinterpret_cast<const float4*>(q)[lane + 32];

    float m = -CUDART_INF_F;
    float l = 0.0f;
    float4 a0 = make_float4(0.f, 0.f, 0.f, 0.f);
    float4 a1 = make_float4(0.f, 0.f, 0.f, 0.f);

    for (int c = bid; c < NCHUNKS; c += NCTA) {
        const int row0 = c * CHUNK_ROWS + warp * RB;

        // -------- K batch: 8 independent LDG.128 --------
        float4 k0[RB], k1[RB];
        #pragma unroll
        for (int j = 0; j < RB; ++j) {
            const float4* Kr =
                reinterpret_cast<const float4*>(K + (size_t)(row0 + j) * DIM);
            k0[j] = Kr[lane];
            k1[j] = Kr[lane + 32];
        }

        float d[RB];
        #pragma unroll
        for (int j = 0; j < RB; ++j) {
            float v = k0[j].x * q0.x + k0[j].y * q0.y + k0[j].z * q0.z + k0[j].w * q0.w
                    + k1[j].x * q1.x + k1[j].y * q1.y + k1[j].z * q1.z + k1[j].w * q1.w;
            #pragma unroll
            for (int off = 16; off > 0; off >>= 1)
                v += __shfl_xor_sync(0xffffffffu, v, off);
            d[j] = v;
        }

        // -------- online softmax update (chunk granularity) --------
        float mc = fmaxf(fmaxf(d[0], d[1]), fmaxf(d[2], d[3]));
        const float mnew  = fmaxf(m, mc);
        const float scale = __expf(m - mnew);   // exp(-inf)=0 on first chunk
        float w[RB];
        #pragma unroll
        for (int j = 0; j < RB; ++j) w[j] = __expf(d[j] - mnew);
        l = l * scale + (w[0] + w[1]) + (w[2] + w[3]);
        m = mnew;

        // -------- V batch: 8 independent LDG.128, weighted accumulate -----
        float4 v0[RB], v1[RB];
        #pragma unroll
        for (int j = 0; j < RB; ++j) {
            const float4* Vr =
                reinterpret_cast<const float4*>(V + (size_t)(row0 + j) * DIM);
            v0[j] = Vr[lane];
            v1[j] = Vr[lane + 32];
        }

        a0.x *= scale; a0.y *= scale; a0.z *= scale; a0.w *= scale;
        a1.x *= scale; a1.y *= scale; a1.z *= scale; a1.w *= scale;
        #pragma unroll
        for (int j = 0; j < RB; ++j) {
            a0.x += w[j] * v0[j].x;  a0.y += w[j] * v0[j].y;
            a0.z += w[j] * v0[j].z;  a0.w += w[j] * v0[j].w;
            a1.x += w[j] * v1[j].x;  a1.y += w[j] * v1[j].y;
            a1.z += w[j] * v1[j].z;  a1.w += w[j] * v1[j].w;
        }
    }

    // ---------------- Merge 8 warps within the CTA ------------------------
    __shared__ float s_m[NWARPS];
    __shared__ float s_l[NWARPS];
    __shared__ float s_acc[NWARPS][DIM];

    if (lane == 0) { s_m[warp] = m; s_l[warp] = l; }
    float* dst = s_acc[warp];
    dst[lane * 4 + 0]       = a0.x;
    dst[lane * 4 + 1]       = a0.y;
    dst[lane * 4 + 2]       = a0.z;
    dst[lane * 4 + 3]       = a0.w;
    dst[128 + lane * 4 + 0] = a1.x;
    dst[128 + lane * 4 + 1] = a1.y;
    dst[128 + lane * 4 + 2] = a1.z;
    dst[128 + lane * 4 + 3] = a1.w;
    __syncthreads();

    float bm = s_m[0];
    #pragma unroll
    for (int w2 = 1; w2 < NWARPS; ++w2) bm = fmaxf(bm, s_m[w2]);

    float y = 0.0f;
    float L = 0.0f;
    #pragma unroll
    for (int w2 = 0; w2 < NWARPS; ++w2) {
        const float sf = __expf(s_m[w2] - bm);
        y += s_acc[w2][tid] * sf;
        L += s_l[w2] * sf;
    }

    g_partT[tid][bid] = y;
    if (tid == 0) {
        g_ml[bid] = make_float2(bm, L);
        atomicMax(&g_gmax_u, enc_f(bm));   // publish global max (1 atomic/CTA)
    }
}

// Tail: 128 blocks x 256 threads; block b handles columns 2b and 2b+1.
// ml loads + exp factors amortized over both columns; one joint reduction
// carrying (ll, acc0, acc1). Last-arriver resets atomics for graph replay.
__global__ __launch_bounds__(256)
void sqa_tail(float* __restrict__ out) {
    const int t    = threadIdx.x;
    const int warp = t >> 5;
    const int lane = t & 31;
    const int c0   = blockIdx.x * 2;
    const int c1   = c0 + 1;

    __shared__ float s8l[NWARPS];
    __shared__ float s8a[NWARPS];
    __shared__ float s8b[NWARPS];

    const bool has3 = (t < NCTA - 512);

    // ---- front-issue ALL loads (independent) ----
    const float  gmax = dec_f(g_gmax_u);
    const float2 ml0  = g_ml[t];
    const float2 ml1  = g_ml[t + 256];
    const float2 ml2  = has3 ? g_ml[t + 512] : make_float2(0.0f, 0.0f);
    const float* rowA = g_partT[c0];
    const float* rowB = g_partT[c1];
    const float  a0v  = rowA[t];
    const float  a1v  = rowA[t + 256];
    const float  a2v  = has3 ? rowA[t + 512] : 0.0f;
    const float  b0v  = rowB[t];
    const float  b1v  = rowB[t + 256];
    const float  b2v  = has3 ? rowB[t + 512] : 0.0f;

    const float e0 = __expf(ml0.x - gmax);
    const float e1 = __expf(ml1.x - gmax);
    const float e2 = has3 ? __expf(ml2.x - gmax) : 0.0f;

    // ---- single JOINT (ll, accA, accB) reduction ----
    float ll   = ml0.y * e0 + ml1.y * e1 + ml2.y * e2;
    float accA = a0v * e0 + a1v * e1 + a2v * e2;
    float accB = b0v * e0 + b1v * e1 + b2v * e2;
    #pragma unroll
    for (int off = 16; off > 0; off >>= 1) {
        ll   += __shfl_xor_sync(0xffffffffu, ll,   off);
        accA += __shfl_xor_sync(0xffffffffu, accA, off);
        accB += __shfl_xor_sync(0xffffffffu, accB, off);
    }
    if (lane == 0) { s8l[warp] = ll; s8a[warp] = accA; s8b[warp] = accB; }
    __syncthreads();
    if (t == 0) {
        const float L = ((s8l[0] + s8l[1]) + (s8l[2] + s8l[3]))
                      + ((s8l[4] + s8l[5]) + (s8l[6] + s8l[7]));
        const float A = ((s8a[0] + s8a[1]) + (s8a[2] + s8a[3]))
                      + ((s8a[4] + s8a[5]) + (s8a[6] + s8a[7]));
        const float B = ((s8b[0] + s8b[1]) + (s8b[2] + s8b[3]))
                      + ((s8b[4] + s8b[5]) + (s8b[6] + s8b[7]));
        const float invL = 1.0f / L;
        out[c0] = A * invL;
        out[c1] = B * invL;

        // Counter-gated reset (each block reads gmax before incrementing).
        if (atomicAdd(&g_cnt, 1u) == (unsigned)(TAIL_BLOCKS - 1)) {
            g_gmax_u = 0u;   // encodes "most negative"
            g_cnt    = 0u;
        }
    }
}

extern "C" void kernel_launch(void* const* d_in, const int* in_sizes, int n_in,
                              void* d_out, int out_size) {
    const float* q = (const float*)d_in[0];
    const float* K = (const float*)d_in[1];
    const float* V = (const float*)d_in[2];
    float* out = (float*)d_out;

    sqa_pass1<<<NCTA, 256>>>(q, K, V);
    sqa_tail<<<TAIL_BLOCKS, 256>>>(out);
}